// round 14
// baseline (speedup 1.0000x reference)
#include <cuda_runtime.h>
#include <cuda_bf16.h>
#include <cstdint>

typedef unsigned long long ull;

// ---------------- scratch (static device globals; no allocations) ----------------
__device__ __nv_bfloat16 g_a1h[800ull * 42 * 42 * 64];      // NHWC bf16 hi/lo
__device__ __nv_bfloat16 g_a1l[800ull * 42 * 42 * 64];
__device__ __nv_bfloat16 g_a2h[800ull * 21 * 21 * 64];
__device__ __nv_bfloat16 g_a2l[800ull * 21 * 21 * 64];
__device__ __nv_bfloat16 g_a3h[800ull * 11 * 11 * 64];
__device__ __nv_bfloat16 g_a3l[800ull * 11 * 11 * 64];
__device__ float g_emb[800ull * 2304];                      // NHWC-flattened (head is order-invariant)
__device__ __nv_bfloat16 g_w1h[64 * 32], g_w1l[64 * 32];    // L1: [oc][k=tap*3+ch, pad 32]
__device__ __nv_bfloat16 g_w2h[9 * 64 * 64], g_w2l[9 * 64 * 64];
__device__ __nv_bfloat16 g_w3h[9 * 64 * 64], g_w3l[9 * 64 * 64];
__device__ __nv_bfloat16 g_w4h[9 * 64 * 64], g_w4l[9 * 64 * 64];
__device__ float g_protos[8 * 5 * 2304];
__device__ float g_pnorm[40];

// ---------------- mma.sync helpers (baseline PTX, no 'a'-target needed) ----------------
#define SWZ(o) ((o) ^ (((o) >> 3) & 0x70))

__device__ __forceinline__ uint32_t smem_u32(const void* p) {
    uint32_t a;
    asm("{ .reg .u64 t; cvta.to.shared.u64 t, %1; cvt.u32.u64 %0, t; }" : "=r"(a) : "l"(p));
    return a;
}
__device__ __forceinline__ void ldsm4(uint32_t& r0, uint32_t& r1, uint32_t& r2, uint32_t& r3,
                                      uint32_t a) {
    asm volatile("ldmatrix.sync.aligned.m8n8.x4.shared.b16 {%0,%1,%2,%3}, [%4];"
                 : "=r"(r0), "=r"(r1), "=r"(r2), "=r"(r3) : "r"(a));
}
__device__ __forceinline__ void mma16816(float* c, const uint32_t* a, const uint32_t* b) {
    asm volatile(
        "mma.sync.aligned.m16n8k16.row.col.f32.bf16.bf16.f32 "
        "{%0,%1,%2,%3}, {%4,%5,%6,%7}, {%8,%9}, {%0,%1,%2,%3};"
        : "+f"(c[0]), "+f"(c[1]), "+f"(c[2]), "+f"(c[3])
        : "r"(a[0]), "r"(a[1]), "r"(a[2]), "r"(a[3]), "r"(b[0]), "r"(b[1]));
}
__device__ __forceinline__ void cpasync16(uint32_t dst, const void* src, uint32_t ssz) {
    asm volatile("cp.async.cg.shared.global [%0], [%1], 16, %2;"
                 :: "r"(dst), "l"(src), "r"(ssz));
}
__device__ __forceinline__ void bf16split(float v, __nv_bfloat16& h, __nv_bfloat16& l) {
    h = __float2bfloat16(v);
    l = __float2bfloat16(v - __bfloat162float(h));
}

// ---------------- weight prep: all layers bf16 hi/lo ----------------
// L1: [oc=64][k=32] with k = (kh*3+kw)*3 + ic (cols 27-31 zero)
// L2-4: [tap=kh*3+kw][oc=64][ic=64]
__global__ void prep_weights(const float* __restrict__ W1, const float* __restrict__ W2,
                             const float* __restrict__ W3, const float* __restrict__ W4)
{
    int i = blockIdx.x * blockDim.x + threadIdx.x;
    if (i < 2048) {
        int oc = i >> 5, k = i & 31;
        float v = 0.f;
        if (k < 27) {
            int t = k / 3, c = k - 3 * t;       // t = kh*3+kw, c = ic
            v = W1[oc * 27 + c * 9 + t];
        }
        __nv_bfloat16 h, l;
        bf16split(v, h, l);
        g_w1h[i] = h; g_w1l[i] = l;
    }
    if (i < 36864) {
        int tap = i >> 12, rem = i & 4095, oc = rem >> 6, ic = rem & 63;
        int kh = tap / 3, kw = tap - kh * 3;
        int s = ((oc * 64 + ic) * 3 + kh) * 3 + kw;
        __nv_bfloat16 h, l;
        bf16split(W2[s], h, l); g_w2h[i] = h; g_w2l[i] = l;
        bf16split(W3[s], h, l); g_w3h[i] = h; g_w3l[i] = l;
        bf16split(W4[s], h, l); g_w4h[i] = h; g_w4l[i] = l;
    }
}

// ---------------- L1 as one GEMM: M=128 pixels x N=64 oc x K=32 (27 used) ----------------
__global__ void __launch_bounds__(128)
conv1_mma(const float* __restrict__ xs, const float* __restrict__ xt,
          const __nv_bfloat16* __restrict__ w1h, const __nv_bfloat16* __restrict__ w1l,
          const float* __restrict__ bias,
          __nv_bfloat16* __restrict__ outh, __nv_bfloat16* __restrict__ outl)
{
    constexpr int NPIX = 42 * 42;   // 1764

    __shared__ __align__(128) __nv_bfloat16 sAh[128 * 64];
    __shared__ __align__(128) __nv_bfloat16 sAl[128 * 64];
    __shared__ __align__(128) __nv_bfloat16 sWh[64 * 64];
    __shared__ __align__(128) __nv_bfloat16 sWl[64 * 64];

    const uint32_t AH = smem_u32(sAh), AL = smem_u32(sAl);
    const uint32_t WH = smem_u32(sWh), WL = smem_u32(sWl);

    const int tid  = threadIdx.x;
    const int lane = tid & 31, w = tid >> 5;
    const int img  = blockIdx.x;
    const int p0   = blockIdx.y * 128;

    // ---- stage A: thread tid owns pixel row tid ----
    {
        const int p  = p0 + tid;
        const bool pv = p < NPIX;
        const int pc = pv ? p : 0;
        const int oh2 = 2 * (pc / 42), ow2 = 2 * (pc % 42);   // PAD=0
        const float* x = (img < 200) ? (xs + (size_t)img * 3 * 7056)
                                     : (xt + (size_t)(img - 200) * 3 * 7056);
#pragma unroll
        for (int k = 0; k < 32; k++) {
            float v = 0.f;
            if (k < 27 && pv) {
                int t = k / 3, c = k - 3 * t;
                int ih = oh2 + t / 3, iw = ow2 + t % 3;
                if (ih < 84 && iw < 84)
                    v = x[(size_t)c * 7056 + ih * 84 + iw];
            }
            __nv_bfloat16 h, l;
            bf16split(v, h, l);
            uint32_t d = SWZ(tid * 128 + (k >> 3) * 16) + (k & 7) * 2;
            asm volatile("st.shared.b16 [%0], %1;" :: "r"(AH + d), "h"(__bfloat16_as_ushort(h)));
            asm volatile("st.shared.b16 [%0], %1;" :: "r"(AL + d), "h"(__bfloat16_as_ushort(l)));
        }
    }
    // ---- stage W ----
    for (int i = tid; i < 512; i += 128) {
        int j = i & 255, row = j >> 2, g = j & 3;
        const __nv_bfloat16* src = (i < 256) ? w1h : w1l;
        uint4 v = *(const uint4*)(src + row * 32 + g * 8);
        uint32_t dst = ((i < 256) ? WH : WL) + SWZ(row * 128 + g * 16);
        asm volatile("st.shared.v4.b32 [%0], {%1, %2, %3, %4};"
                     :: "r"(dst), "r"(v.x), "r"(v.y), "r"(v.z), "r"(v.w));
    }
    __syncthreads();

    float acc[2][8][4];
#pragma unroll
    for (int mt = 0; mt < 2; mt++)
#pragma unroll
        for (int nt = 0; nt < 8; nt++)
#pragma unroll
            for (int q = 0; q < 4; q++) acc[mt][nt][q] = 0.f;

    const int aRow = lane & 15;
    const int aK   = (lane & 16) ? 16 : 0;
    const int bRow = (lane & 7) + ((lane & 16) ? 8 : 0);
    const int bK   = (lane & 8) ? 16 : 0;

    // fragment-hoisted: load A_hi/A_lo/W_hi/W_lo once per k-step, 3 split-MMAs from regs
#pragma unroll
    for (int ks = 0; ks < 2; ++ks) {
        const int kb = ks * 32;
        uint32_t bh[8][2], bl[8][2];
#pragma unroll
        for (int np = 0; np < 4; ++np) {
            uint32_t so = SWZ((np * 16 + bRow) * 128 + kb + bK);
            ldsm4(bh[2 * np][0], bh[2 * np][1], bh[2 * np + 1][0], bh[2 * np + 1][1], WH + so);
            ldsm4(bl[2 * np][0], bl[2 * np][1], bl[2 * np + 1][0], bl[2 * np + 1][1], WL + so);
        }
#pragma unroll
        for (int mt = 0; mt < 2; ++mt) {
            uint32_t ah_[4], al_[4];
            uint32_t so = SWZ((w * 32 + mt * 16 + aRow) * 128 + kb + aK);
            ldsm4(ah_[0], ah_[1], ah_[2], ah_[3], AH + so);
            ldsm4(al_[0], al_[1], al_[2], al_[3], AL + so);
#pragma unroll
            for (int nt = 0; nt < 8; ++nt) {
                mma16816(acc[mt][nt], ah_, bh[nt]);
                mma16816(acc[mt][nt], al_, bh[nt]);
                mma16816(acc[mt][nt], ah_, bl[nt]);
            }
        }
    }

    // epilogue: bias + relu -> NHWC bf16 hi/lo
#pragma unroll
    for (int mt = 0; mt < 2; ++mt) {
        int r = w * 32 + mt * 16 + (lane >> 2);
#pragma unroll
        for (int half = 0; half < 2; ++half) {
            int pp = p0 + r + half * 8;
            if (pp >= NPIX) continue;
#pragma unroll
            for (int nt = 0; nt < 8; ++nt) {
                int col = nt * 8 + (lane & 3) * 2;
                float v0 = fmaxf(acc[mt][nt][half * 2 + 0] + bias[col],     0.f);
                float v1 = fmaxf(acc[mt][nt][half * 2 + 1] + bias[col + 1], 0.f);
                __nv_bfloat16 h0, l0, h1, l1;
                bf16split(v0, h0, l0);
                bf16split(v1, h1, l1);
                uint32_t hp = (uint32_t)__bfloat16_as_ushort(h0) |
                              ((uint32_t)__bfloat16_as_ushort(h1) << 16);
                uint32_t lp = (uint32_t)__bfloat16_as_ushort(l0) |
                              ((uint32_t)__bfloat16_as_ushort(l1) << 16);
                *(uint32_t*)(outh + ((size_t)img * NPIX + pp) * 64 + col) = hp;
                *(uint32_t*)(outl + ((size_t)img * NPIX + pp) * 64 + col) = lp;
            }
        }
    }
}

// ---------------- mma.sync implicit-GEMM conv, cp.async double-buffered (L2-L4) ----------------
template<int INW, int OUTW, int PAD, bool OUT_FP32>
__global__ void __launch_bounds__(128)
conv_mma(const __nv_bfloat16* __restrict__ ah, const __nv_bfloat16* __restrict__ al,
         const __nv_bfloat16* __restrict__ wh, const __nv_bfloat16* __restrict__ wl,
         const float* __restrict__ bias,
         __nv_bfloat16* __restrict__ outh, __nv_bfloat16* __restrict__ outl,
         float* __restrict__ outf)
{
    constexpr int NPIX = OUTW * OUTW;

    extern __shared__ char dsm[];
    const uint32_t base = (smem_u32(dsm) + 1023) & ~1023u;
    const uint32_t AH = base, AL = base + 32768, WH = base + 65536, WL = base + 81920;

    const int tid  = threadIdx.x;
    const int lane = tid & 31, w = tid >> 5;
    const int img  = blockIdx.x;
    const int p0   = blockIdx.y * 128;

    const int  p   = p0 + tid;
    const bool pv  = p < NPIX;
    const int  pc  = pv ? p : 0;
    const int  oh2 = 2 * (pc / OUTW) - PAD;
    const int  ow2 = 2 * (pc % OUTW) - PAD;
    const size_t imgbase = (size_t)img * INW * INW * 64;
    const int  wrow = tid >> 1, wc0 = (tid & 1) * 4;

    auto stage = [&](int tap, int sel) {
        const int kh = tap / 3, kw = tap - kh * 3;
        const int ih = oh2 + kh, iw = ow2 + kw;
        const bool valid = pv && (unsigned)ih < (unsigned)INW && (unsigned)iw < (unsigned)INW;
        const uint32_t ssz = valid ? 16u : 0u;
        const size_t off = valid ? (imgbase + ((size_t)ih * INW + iw) * 64) : imgbase;
        const __nv_bfloat16* sh_ = ah + off;
        const __nv_bfloat16* sl_ = al + off;
        const uint32_t dh_ = AH + sel * 16384;
        const uint32_t dl_ = AL + sel * 16384;
#pragma unroll
        for (int c = 0; c < 8; c++) {
            uint32_t d = SWZ(tid * 128 + c * 16);
            cpasync16(dh_ + d, sh_ + c * 8, ssz);
            cpasync16(dl_ + d, sl_ + c * 8, ssz);
        }
        const __nv_bfloat16* wsh = wh + tap * 4096 + wrow * 64 + wc0 * 8;
        const __nv_bfloat16* wsl = wl + tap * 4096 + wrow * 64 + wc0 * 8;
        const uint32_t dwh = WH + sel * 8192, dwl = WL + sel * 8192;
#pragma unroll
        for (int c = 0; c < 4; c++) {
            uint32_t d = SWZ(wrow * 128 + (wc0 + c) * 16);
            cpasync16(dwh + d, wsh + c * 8, 16u);
            cpasync16(dwl + d, wsl + c * 8, 16u);
        }
    };

    float acc[2][8][4];
#pragma unroll
    for (int mt = 0; mt < 2; mt++)
#pragma unroll
        for (int nt = 0; nt < 8; nt++)
#pragma unroll
            for (int q = 0; q < 4; q++) acc[mt][nt][q] = 0.f;

    const int aRow = lane & 15;
    const int aK   = (lane & 16) ? 16 : 0;
    const int bRow = (lane & 7) + ((lane & 16) ? 8 : 0);
    const int bK   = (lane & 8) ? 16 : 0;

    stage(0, 0);
    asm volatile("cp.async.commit_group;" ::: "memory");

    for (int tap = 0; tap < 9; ++tap) {
        const int sel = tap & 1;
        if (tap < 8) {
            stage(tap + 1, sel ^ 1);
            asm volatile("cp.async.commit_group;" ::: "memory");
            asm volatile("cp.async.wait_group 1;" ::: "memory");
        } else {
            asm volatile("cp.async.wait_group 0;" ::: "memory");
        }
        __syncthreads();

        const uint32_t AHs = AH + sel * 16384, ALs = AL + sel * 16384;
        const uint32_t WHs = WH + sel * 8192,  WLs = WL + sel * 8192;

        // fragment-hoisted inner loop: 12 ldsm4 + 48 mma per k-step
#pragma unroll
        for (int ks = 0; ks < 4; ++ks) {
            const int kb = ks * 32;
            uint32_t bh[8][2], bl[8][2];
#pragma unroll
            for (int np = 0; np < 4; ++np) {
                uint32_t so = SWZ((np * 16 + bRow) * 128 + kb + bK);
                ldsm4(bh[2 * np][0], bh[2 * np][1], bh[2 * np + 1][0], bh[2 * np + 1][1], WHs + so);
                ldsm4(bl[2 * np][0], bl[2 * np][1], bl[2 * np + 1][0], bl[2 * np + 1][1], WLs + so);
            }
#pragma unroll
            for (int mt = 0; mt < 2; ++mt) {
                uint32_t ah_[4], al_[4];
                uint32_t so = SWZ((w * 32 + mt * 16 + aRow) * 128 + kb + aK);
                ldsm4(ah_[0], ah_[1], ah_[2], ah_[3], AHs + so);
                ldsm4(al_[0], al_[1], al_[2], al_[3], ALs + so);
#pragma unroll
                for (int nt = 0; nt < 8; ++nt) {
                    mma16816(acc[mt][nt], ah_, bh[nt]);
                    mma16816(acc[mt][nt], al_, bh[nt]);
                    mma16816(acc[mt][nt], ah_, bl[nt]);
                }
            }
        }
        __syncthreads();
    }

    // epilogue: bias + relu
#pragma unroll
    for (int mt = 0; mt < 2; ++mt) {
        int r = w * 32 + mt * 16 + (lane >> 2);
#pragma unroll
        for (int half = 0; half < 2; ++half) {
            int pp = p0 + r + half * 8;
            if (pp >= NPIX) continue;
#pragma unroll
            for (int nt = 0; nt < 8; ++nt) {
                int col = nt * 8 + (lane & 3) * 2;
                float v0 = fmaxf(acc[mt][nt][half * 2 + 0] + bias[col],     0.f);
                float v1 = fmaxf(acc[mt][nt][half * 2 + 1] + bias[col + 1], 0.f);
                if (OUT_FP32) {
                    float2* o = (float2*)(outf + ((size_t)img * NPIX + pp) * 64 + col);
                    *o = make_float2(v0, v1);
                } else {
                    __nv_bfloat16 h0, l0, h1, l1;
                    bf16split(v0, h0, l0);
                    bf16split(v1, h1, l1);
                    uint32_t hp = (uint32_t)__bfloat16_as_ushort(h0) |
                                  ((uint32_t)__bfloat16_as_ushort(h1) << 16);
                    uint32_t lp = (uint32_t)__bfloat16_as_ushort(l0) |
                                  ((uint32_t)__bfloat16_as_ushort(l1) << 16);
                    *(uint32_t*)(outh + ((size_t)img * NPIX + pp) * 64 + col) = hp;
                    *(uint32_t*)(outl + ((size_t)img * NPIX + pp) * 64 + col) = lp;
                }
            }
        }
    }
}

// ---------------- prototypes / norms / logits (NHWC order-invariant) ----------------
__global__ void proto_kernel(const float* __restrict__ emb_s, const int* __restrict__ y,
                             float* __restrict__ protos)
{
    int b = blockIdx.x, c = blockIdx.y;
    for (int d = threadIdx.x; d < 2304; d += blockDim.x) {
        float acc = 0.f;
#pragma unroll
        for (int s = 0; s < 25; s++) {
            if ((y[b * 25 + s] % 5) == c)
                acc += emb_s[(size_t)(b * 25 + s) * 2304 + d];
        }
        protos[(size_t)(b * 5 + c) * 2304 + d] = acc * 0.2f;
    }
}

__device__ __forceinline__ float block_reduce(float v, float* red) {
    red[threadIdx.x] = v;
    __syncthreads();
    for (int s = 128; s > 0; s >>= 1) {
        if (threadIdx.x < s) red[threadIdx.x] += red[threadIdx.x + s];
        __syncthreads();
    }
    float r = red[0];
    __syncthreads();
    return r;
}

__global__ void pnorm_kernel(const float* __restrict__ protos, float* __restrict__ pnorm) {
    __shared__ float red[256];
    const float* p = protos + (size_t)blockIdx.x * 2304;
    float s = 0.f;
    for (int d = threadIdx.x; d < 2304; d += 256) { float v = p[d]; s += v * v; }
    float tot = block_reduce(s, red);
    if (threadIdx.x == 0) pnorm[blockIdx.x] = fmaxf(sqrtf(tot), 1e-8f);
}

__global__ void logits_kernel(const float* __restrict__ emb, const float* __restrict__ protos,
                              const float* __restrict__ pnorm, float* __restrict__ out)
{
    __shared__ float red[256];
    int b = blockIdx.x / 75, t = blockIdx.x % 75;
    const float* q = emb + (size_t)(200 + b * 75 + t) * 2304;
    const float* P = protos + (size_t)b * 5 * 2304;

    float q2 = 0.f, dot[5] = {0.f, 0.f, 0.f, 0.f, 0.f};
    for (int d = threadIdx.x; d < 2304; d += 256) {
        float v = q[d];
        q2 += v * v;
#pragma unroll
        for (int c = 0; c < 5; c++) dot[c] += v * P[(size_t)c * 2304 + d];
    }
    float q2t = block_reduce(q2, red);
    float qn  = fmaxf(sqrtf(q2t), 1e-8f);
#pragma unroll
    for (int c = 0; c < 5; c++) {
        float dt = block_reduce(dot[c], red);
        if (threadIdx.x == 0)
            out[(size_t)(b * 75 + t) * 5 + c] = dt / (qn * pnorm[b * 5 + c]);
    }
}

// ---------------- launch ----------------
extern "C" void kernel_launch(void* const* d_in, const int* in_sizes, int n_in,
                              void* d_out, int out_size)
{
    const float* xs = (const float*)d_in[0];
    const float* xt = (const float*)d_in[1];
    const int*   y  = (const int*)  d_in[2];
    const float* W1 = (const float*)d_in[3];
    const float* b1 = (const float*)d_in[4];
    const float* W2 = (const float*)d_in[5];
    const float* b2 = (const float*)d_in[6];
    const float* W3 = (const float*)d_in[7];
    const float* b3 = (const float*)d_in[8];
    const float* W4 = (const float*)d_in[9];
    const float* b4 = (const float*)d_in[10];
    float* out = (float*)d_out;

    float *emb, *protos, *pnorm;
    __nv_bfloat16 *a1h, *a1l, *a2h, *a2l, *a3h, *a3l;
    __nv_bfloat16 *w1h, *w1l, *w2h, *w2l, *w3h, *w3l, *w4h, *w4l;
    cudaGetSymbolAddress((void**)&a1h,    g_a1h);
    cudaGetSymbolAddress((void**)&a1l,    g_a1l);
    cudaGetSymbolAddress((void**)&a2h,    g_a2h);
    cudaGetSymbolAddress((void**)&a2l,    g_a2l);
    cudaGetSymbolAddress((void**)&a3h,    g_a3h);
    cudaGetSymbolAddress((void**)&a3l,    g_a3l);
    cudaGetSymbolAddress((void**)&emb,    g_emb);
    cudaGetSymbolAddress((void**)&w1h,    g_w1h);
    cudaGetSymbolAddress((void**)&w1l,    g_w1l);
    cudaGetSymbolAddress((void**)&w2h,    g_w2h);
    cudaGetSymbolAddress((void**)&w2l,    g_w2l);
    cudaGetSymbolAddress((void**)&w3h,    g_w3h);
    cudaGetSymbolAddress((void**)&w3l,    g_w3l);
    cudaGetSymbolAddress((void**)&w4h,    g_w4h);
    cudaGetSymbolAddress((void**)&w4l,    g_w4l);
    cudaGetSymbolAddress((void**)&protos, g_protos);
    cudaGetSymbolAddress((void**)&pnorm,  g_pnorm);

    auto c2 = conv_mma<42, 21, 0, false>;
    auto c3 = conv_mma<21, 11, 1, false>;
    auto c4 = conv_mma<11, 6,  1, true>;
    const int DSMEM = 98304 + 1024;
    static int attr_done = 0;
    if (!attr_done) {
        cudaFuncSetAttribute((const void*)c2, cudaFuncAttributeMaxDynamicSharedMemorySize, DSMEM);
        cudaFuncSetAttribute((const void*)c3, cudaFuncAttributeMaxDynamicSharedMemorySize, DSMEM);
        cudaFuncSetAttribute((const void*)c4, cudaFuncAttributeMaxDynamicSharedMemorySize, DSMEM);
        attr_done = 1;
    }

    prep_weights<<<(36864 + 255) / 256, 256>>>(W1, W2, W3, W4);

    // L1: single-GEMM mma conv, writes NHWC bf16 hi/lo directly
    conv1_mma<<<dim3(800, 14), 128>>>(xs, xt, w1h, w1l, b1, a1h, a1l);

    // L2-L4: mma.sync implicit-GEMM convs (bf16 3-split, cp.async pipelined)
    c2<<<dim3(800, 4), 128, DSMEM>>>(a1h, a1l, w2h, w2l, b2, a2h, a2l, nullptr);
    c3<<<dim3(800, 1), 128, DSMEM>>>(a2h, a2l, w3h, w3l, b3, a3h, a3l, nullptr);
    c4<<<dim3(800, 1), 128, DSMEM>>>(a3h, a3l, w4h, w4l, b4, nullptr, nullptr, emb);

    proto_kernel<<<dim3(8, 5), 256>>>(emb, y, protos);
    pnorm_kernel<<<40, 256>>>(protos, pnorm);
    logits_kernel<<<600, 256>>>(emb, protos, pnorm, out);
}